// round 8
// baseline (speedup 1.0000x reference)
#include <cuda_runtime.h>
#include <cstdint>

// Problem constants
#define BATCH 64
#define M     4096   // NPROP (columns)
#define NGTC  128    // max GT (rows)
#define NT    512    // threads per CTA
#define CPT   (M/NT) // 8 columns per thread
#define NW    (NT/32)

// Order-preserving double <-> uint64 (total order identical to operator< on doubles)
__device__ __forceinline__ unsigned long long ord64(double x) {
    long long s = __double_as_longlong(x);
    return (unsigned long long)s ^ ((unsigned long long)(s >> 63) | 0x8000000000000000ull);
}
__device__ __forceinline__ double unord64(unsigned long long k) {
    long long b = (k & 0x8000000000000000ull) ? (long long)(k ^ 0x8000000000000000ull)
                                              : (long long)(~k);
    return __longlong_as_double(b);
}

#define KINF 0xFFFFFFFFFFFFFFFFull

__global__ __launch_bounds__(NT, 1)
void matcher_kernel(const int*   __restrict__ nag,   // [B]
                    const float* __restrict__ gtn,   // [B][NGT][3]
                    const float* __restrict__ qn,    // [M][3]
                    float*       __restrict__ out)   // [2][B][M] : inds then mask
{
    const int b    = blockIdx.x;
    const int tid  = threadIdx.x;
    const int lane = tid & 31;
    const int wid  = tid >> 5;

    __shared__ short              p[M + 1];      // column -> matched row (1-based), 0 = free
    __shared__ unsigned short     way[M + 1];    // predecessor column (0 = from cur_row)
    __shared__ double             u[NGTC + 1];   // row duals (1-based)
    __shared__ float              gns[NGTC * 3]; // gt normals for this batch
    __shared__ unsigned long long wkey[2][NW];   // per-warp min key (parity-buffered)
    __shared__ int                wjj[2][NW];    // per-warp argmin column

    const int k = nag[b];

    // ---- init shared state ----
    for (int j = tid; j <= M; j += NT) p[j] = 0;
    for (int j = tid; j <= NGTC; j += NT) u[j] = 0.0;
    for (int j = tid; j < k * 3; j += NT) gns[j] = gtn[(size_t)b * NGTC * 3 + j];

    // ---- per-thread register state (8 columns, strided by NT) ----
    float  q0[CPT], q1[CPT], q2[CPT];
    double v[CPT];                       // column duals (double)
    unsigned long long dkey[CPT];        // shortest-path cost as ordered uint64 key
    #pragma unroll
    for (int t = 0; t < CPT; t++) {
        int c = tid + t * NT;
        q0[t] = qn[c * 3 + 0];
        q1[t] = qn[c * 3 + 1];
        q2[t] = qn[c * 3 + 2];
        v[t]  = 0.0;
    }
    __syncthreads();

    int par = 0;   // parity for double-buffered reduction scratch

    // ---- LAPJV shortest augmenting path, one row per phase ----
    for (int i = 1; i <= k; i++) {
        unsigned usedmask = 0;
        #pragma unroll
        for (int t = 0; t < CPT; t++) dkey[t] = KINF;

        int    i0 = i, j0 = 0, jend = 0;
        double minVal = 0.0;

        while (true) {
            // uniform per-step scalars (u constant during a phase)
            const double h1 = minVal - u[i0] + 1.0;   // folds the "1 - dot" constant
            const float  gx = gns[(i0 - 1) * 3 + 0];
            const float  gy = gns[(i0 - 1) * 3 + 1];
            const float  gz = gns[(i0 - 1) * 3 + 2];

            // relax free columns; all compares/argmin on integer keys (ALU pipe)
            unsigned long long bestkey = KINF;
            int bestj = M + 1;
            #pragma unroll
            for (int t = 0; t < CPT; t++) {
                int   j   = tid + t * NT + 1;
                float dot = fmaf(q2[t], gz, fmaf(q1[t], gy, q0[t] * gx));
                double r  = (h1 - v[t]) - (double)dot;  // minVal + (1-dot) - u[i0] - v[j]
                unsigned long long rk = ord64(r);
                if (!((usedmask >> t) & 1u)) {
                    if (rk < dkey[t]) { dkey[t] = rk; way[j] = (unsigned short)j0; }
                    // per-thread js ascend with t, so strict < keeps smallest j on ties
                    if (dkey[t] < bestkey) { bestkey = dkey[t]; bestj = j; }
                }
            }
            // warp argmin on (uint64 key, index) — integer compares only
            #pragma unroll
            for (int off = 16; off; off >>= 1) {
                unsigned long long ok = __shfl_down_sync(0xFFFFFFFFu, bestkey, off);
                int                oj = __shfl_down_sync(0xFFFFFFFFu, bestj,   off);
                if (ok < bestkey || (ok == bestkey && oj < bestj)) { bestkey = ok; bestj = oj; }
            }
            if (lane == 0) { wkey[par][wid] = bestkey; wjj[par][wid] = bestj; }
            __syncthreads();   // the ONLY barrier in the step

            // every warp reduces the 16 partials redundantly (parity buffer makes
            // cross-step reuse safe without a second barrier)
            unsigned long long bk = (lane < NW) ? wkey[par][lane] : KINF;
            int                bj = (lane < NW) ? wjj[par][lane]  : (M + 1);
            #pragma unroll
            for (int off = 8; off; off >>= 1) {
                unsigned long long ok = __shfl_down_sync(0xFFFFFFFFu, bk, off);
                int                oj = __shfl_down_sync(0xFFFFFFFFu, bj, off);
                if (ok < bk || (ok == bk && oj < bj)) { bk = ok; bj = oj; }
            }
            const unsigned long long fkey = __shfl_sync(0xFFFFFFFFu, bk, 0);
            const int                j1   = __shfl_sync(0xFFFFFFFFu, bj, 0);
            minVal = unord64(fkey);
            par ^= 1;

            const int pmatch = p[j1];        // p stable during the phase
            if (pmatch == 0) { jend = j1; break; }

            // mark j1 scanned (register bitmask on owning thread)
            { int c = j1 - 1; if ((c & (NT - 1)) == tid) usedmask |= 1u << (c >> 9); }
            i0 = pmatch;
            j0 = j1;
        }

        // ---- phase-end dual updates (scanned set only), BEFORE augmentation ----
        #pragma unroll
        for (int t = 0; t < CPT; t++) {
            if ((usedmask >> t) & 1u) {
                double adj = minVal - unord64(dkey[t]);
                v[t] -= adj;                         // v[j] -= minVal - d[j]
                int j = tid + t * NT + 1;
                u[p[j]] += adj;                      // distinct rows across scanned cols
            }
        }
        if (tid == 0) u[i] += minVal;
        __syncthreads();                             // u writes + p/way reads done

        if (tid == 0) {                              // augment along predecessor chain
            int j = jend;
            while (true) {
                int jp = way[j];
                if (jp == 0) { p[j] = (short)i; break; }
                p[j] = p[jp];
                j = jp;
            }
        }
        __syncthreads();                             // p/way stable before next phase
    }

    // ---- write outputs: [0] per_prop_gt_inds, [1] proposal_matched_mask ----
    float* outInds = out + (size_t)b * M;
    float* outMask = out + (size_t)BATCH * M + (size_t)b * M;
    #pragma unroll
    for (int t = 0; t < CPT; t++) {
        int c = tid + t * NT;
        int r = p[c + 1];
        outInds[c] = (r > 0) ? (float)(r - 1) : 0.0f;
        outMask[c] = (r > 0) ? 1.0f : 0.0f;
    }
}

extern "C" void kernel_launch(void* const* d_in, const int* in_sizes, int n_in,
                              void* d_out, int out_size) {
    // metadata order: cls_prob[0], gt_box_present[1], num_actual_gt[2],
    //                 gt_normal_normalized[3], query_normals[4]
    const int*   nag = (const int*)  d_in[2];
    const float* gtn = (const float*)d_in[3];
    const float* qn  = (const float*)d_in[4];
    matcher_kernel<<<BATCH, NT>>>(nag, gtn, qn, (float*)d_out);
}